// round 15
// baseline (speedup 1.0000x reference)
#include <cuda_runtime.h>
#include <cuda_bf16.h>
#include <cstdint>
#include <math_constants.h>

#define BATCH 4
#define SEQ   4096
#define EMB   1024
#define ROWS  (BATCH * SEQ)      // 16384
#define SCALE 0.03125f           // 1/sqrt(1024)

// GEMM tiling: CTA 128x128, 256 threads (2x4 warps, warp tile 64x32),
// 2-stage cp.async double buffer, 2 CTAs per SM.
#define CTM 128
#define CTN 128
#define KSTAGE 32
#define NSTAGES 2
#define KSTEPS (EMB / KSTAGE)    // 32
#define NTHREADS 256

#define ROWSTRIDE_B 80           // bytes (32 bf16 + pad)
#define MAT_BYTES  (128 * ROWSTRIDE_B)       // 10240
#define STAGE_BYTES (4 * MAT_BYTES)          // 40960
#define DSMEM_BYTES (NSTAGES * STAGE_BYTES)  // 81920 per CTA -> 2 CTAs/SM

// ---------------------------------------------------------------------------
// Scratch (device globals)
// ---------------------------------------------------------------------------
__device__ __nv_bfloat16 g_Xhi[(size_t)ROWS * EMB];
__device__ __nv_bfloat16 g_Xlo[(size_t)ROWS * EMB];
__device__ __nv_bfloat16 g_Wq_hi[EMB * EMB], g_Wq_lo[EMB * EMB];
__device__ __nv_bfloat16 g_Wk_hi[EMB * EMB], g_Wk_lo[EMB * EMB];
__device__ __nv_bfloat16 g_Mt_hi[EMB * EMB], g_Mt_lo[EMB * EMB];   // (Wk Wq^T)/32
__device__ __nv_bfloat16 g_Yhi[(size_t)ROWS * EMB], g_Ylo[(size_t)ROWS * EMB];
__device__ float g_vmean[ROWS];
__device__ float g_wvbar[EMB];
// online-softmax merge state (per output row)
__device__ unsigned int g_lock[ROWS];
__device__ float g_M[ROWS];
__device__ float g_S0[ROWS];
__device__ float g_S1[ROWS];

// ---------------------------------------------------------------------------
// Helpers
// ---------------------------------------------------------------------------
__device__ __forceinline__ uint32_t smem_u32(const void* p) {
    uint32_t a;
    asm("{ .reg .u64 t; cvta.to.shared.u64 t, %1; cvt.u32.u64 %0, t; }" : "=r"(a) : "l"(p));
    return a;
}
__device__ __forceinline__ void cp_async16(uint32_t dst, const void* src) {
    asm volatile("cp.async.cg.shared.global [%0], [%1], 16;" :: "r"(dst), "l"(src) : "memory");
}
__device__ __forceinline__ void cp_commit() {
    asm volatile("cp.async.commit_group;" ::: "memory");
}
template <int NN>
__device__ __forceinline__ void cp_wait() {
    asm volatile("cp.async.wait_group %0;" :: "n"(NN) : "memory");
}
__device__ __forceinline__ void ldm_x4(uint32_t* r, uint32_t addr) {
    asm volatile("ldmatrix.sync.aligned.m8n8.x4.shared.b16 {%0,%1,%2,%3}, [%4];"
                 : "=r"(r[0]), "=r"(r[1]), "=r"(r[2]), "=r"(r[3]) : "r"(addr));
}
__device__ __forceinline__ void mma16816(float* c, const uint32_t* a, uint32_t b0, uint32_t b1) {
    asm volatile("mma.sync.aligned.m16n8k16.row.col.f32.bf16.bf16.f32 "
                 "{%0,%1,%2,%3}, {%4,%5,%6,%7}, {%8,%9}, {%0,%1,%2,%3};"
                 : "+f"(c[0]), "+f"(c[1]), "+f"(c[2]), "+f"(c[3])
                 : "r"(a[0]), "r"(a[1]), "r"(a[2]), "r"(a[3]), "r"(b0), "r"(b1));
}
__device__ __forceinline__ uint32_t packbf(__nv_bfloat16 a, __nv_bfloat16 b) {
    __nv_bfloat162 t = __halves2bfloat162(a, b);
    return *reinterpret_cast<uint32_t*>(&t);
}

// ---------------------------------------------------------------------------
// prep1: range-branched mega-kernel
// ---------------------------------------------------------------------------
#define P_SPLIT_END 16384
#define P_WQ_END    17408
#define P_WK_END    18432
#define P_WV_END    18560
#define P_SM_END    18624          // softmax-state init: 64 blocks x 256 = 16384

__device__ __forceinline__ void split4(const float4* __restrict__ src,
                                       uint2* __restrict__ hi, uint2* __restrict__ lo, int i) {
    float4 v = src[i];
    __nv_bfloat16 h0 = __float2bfloat16(v.x), h1 = __float2bfloat16(v.y);
    __nv_bfloat16 h2 = __float2bfloat16(v.z), h3 = __float2bfloat16(v.w);
    __nv_bfloat16 l0 = __float2bfloat16(v.x - __bfloat162float(h0));
    __nv_bfloat16 l1 = __float2bfloat16(v.y - __bfloat162float(h1));
    __nv_bfloat16 l2 = __float2bfloat16(v.z - __bfloat162float(h2));
    __nv_bfloat16 l3 = __float2bfloat16(v.w - __bfloat162float(h3));
    hi[i] = make_uint2(packbf(h0, h1), packbf(h2, h3));
    lo[i] = make_uint2(packbf(l0, l1), packbf(l2, l3));
}

__global__ __launch_bounds__(256)
void prep1_kernel(const float* __restrict__ X,
                  const float* __restrict__ Wq,
                  const float* __restrict__ Wk,
                  const float* __restrict__ Wv) {
    const int b = blockIdx.x;
    if (b < P_SPLIT_END) {
        split4((const float4*)X, (uint2*)g_Xhi, (uint2*)g_Xlo, b * 256 + threadIdx.x);
    } else if (b < P_WQ_END) {
        split4((const float4*)Wq, (uint2*)g_Wq_hi, (uint2*)g_Wq_lo,
               (b - P_SPLIT_END) * 256 + threadIdx.x);
    } else if (b < P_WK_END) {
        split4((const float4*)Wk, (uint2*)g_Wk_hi, (uint2*)g_Wk_lo,
               (b - P_WQ_END) * 256 + threadIdx.x);
    } else if (b < P_WV_END) {
        int row = (b - P_WK_END) * 8 + (threadIdx.x >> 5);
        int lane = threadIdx.x & 31;
        const float* p = Wv + (size_t)row * EMB;
        float s = 0.f;
        #pragma unroll 4
        for (int j = lane; j < EMB; j += 32) s += p[j];
        #pragma unroll
        for (int o = 16; o > 0; o >>= 1) s += __shfl_xor_sync(0xffffffffu, s, o);
        if (lane == 0) g_wvbar[row] = s * (1.0f / (float)EMB);
    } else {
        int i = (b - P_WV_END) * 256 + threadIdx.x;
        g_lock[i] = 0u;
        g_M[i] = -CUDART_INF_F;
        g_S0[i] = 0.f;
        g_S1[i] = 0.f;
    }
}

__global__ void vmean_kernel(const float* __restrict__ X) {
    int row = blockIdx.x * (blockDim.x >> 5) + (threadIdx.x >> 5);
    int lane = threadIdx.x & 31;
    if (row >= ROWS) return;
    const float4* p = (const float4*)(X + (size_t)row * EMB);
    const float4* w = (const float4*)g_wvbar;
    float s = 0.f;
    #pragma unroll 8
    for (int j = lane; j < EMB / 4; j += 32) {
        float4 a = p[j], b = w[j];
        s += a.x * b.x + a.y * b.y + a.z * b.z + a.w * b.w;
    }
    #pragma unroll
    for (int o = 16; o > 0; o >>= 1) s += __shfl_xor_sync(0xffffffffu, s, o);
    if (lane == 0) g_vmean[row] = s;
}

// ---------------------------------------------------------------------------
// bf16x2-split NT GEMM: 256 threads, 2x4 warps, warp tile 64x32,
// 2-stage double buffer, 2 CTAs/SM.
// mode 0: write C as split bf16 (scaled)
// mode 1: FUSED online softmax — no C write; merges (max, sum_exp, sum_exp*vm)
//         per row into g_M/g_S0/g_S1 under per-row locks.
// ---------------------------------------------------------------------------
__global__ __launch_bounds__(NTHREADS, 2)
void gemm_nt_mma(const __nv_bfloat16* __restrict__ Ahi, const __nv_bfloat16* __restrict__ Alo,
                 const __nv_bfloat16* __restrict__ Bhi, const __nv_bfloat16* __restrict__ Blo,
                 size_t aBatch, size_t bBatch, int mode, float scale,
                 __nv_bfloat16* __restrict__ Chi, __nv_bfloat16* __restrict__ Clo) {
    extern __shared__ char smem[];
    const uint32_t sbase = smem_u32(smem);
    const int tid = threadIdx.x;
    const int lane = tid & 31;
    const int wid = tid >> 5;
    const int wm = wid >> 2;          // 0..1  -> 64 rows each
    const int wn = wid & 3;           // 0..3  -> 32 cols each
    const int bz = blockIdx.z;
    const int mBase = blockIdx.y * CTM;
    const int nBase = blockIdx.x * CTN;

    const __nv_bfloat16* gsrc[4];
    gsrc[0] = Ahi + (size_t)bz * aBatch + (size_t)mBase * EMB;
    gsrc[1] = Alo + (size_t)bz * aBatch + (size_t)mBase * EMB;
    gsrc[2] = Bhi + (size_t)bz * bBatch + (size_t)nBase * EMB;
    gsrc[3] = Blo + (size_t)bz * bBatch + (size_t)nBase * EMB;

    const int r0 = tid >> 2, s0i = tid & 3;
    const int r1 = 64 + (tid >> 2);

    const uint32_t aRowOff = (uint32_t)(wm * 64 + (lane & 15)) * ROWSTRIDE_B;
    const uint32_t aKsel = ((lane >> 4) & 1) * 16;
    const uint32_t bRowOff = (uint32_t)(wn * 32 + ((lane >> 4) & 1) * 8 + (lane & 7)) * ROWSTRIDE_B;
    const uint32_t bKsel = ((lane >> 3) & 1) * 16;

    float acc[4][4][4];
    #pragma unroll
    for (int i = 0; i < 4; i++)
        #pragma unroll
        for (int j = 0; j < 4; j++)
            #pragma unroll
            for (int q = 0; q < 4; q++) acc[i][j][q] = 0.f;

    auto load_stage = [&](int k0, int buf) {
        uint32_t sb = sbase + buf * STAGE_BYTES;
        #pragma unroll
        for (int m = 0; m < 4; m++) {
            const __nv_bfloat16* g = gsrc[m] + k0 * KSTAGE;
            cp_async16(sb + m * MAT_BYTES + r0 * ROWSTRIDE_B + s0i * 16,
                       g + (size_t)r0 * EMB + s0i * 8);
            cp_async16(sb + m * MAT_BYTES + r1 * ROWSTRIDE_B + s0i * 16,
                       g + (size_t)r1 * EMB + s0i * 8);
        }
    };

    load_stage(0, 0);
    cp_commit();

    for (int k0 = 0; k0 < KSTEPS; k0++) {
        cp_wait<0>();
        __syncthreads();
        if (k0 + 1 < KSTEPS)
            load_stage(k0 + 1, (k0 + 1) & 1);
        cp_commit();

        const uint32_t sb = sbase + (k0 & 1) * STAGE_BYTES;
        #pragma unroll
        for (int kk = 0; kk < 2; kk++) {
            const uint32_t kByte = kk * 32;
            uint32_t ah[4][4], al[4][4], bh[8], bl[8];
            #pragma unroll
            for (int mt = 0; mt < 4; mt++) {
                uint32_t ao = aRowOff + (uint32_t)(mt * 16) * ROWSTRIDE_B + kByte + aKsel;
                ldm_x4(ah[mt], sb + 0 * MAT_BYTES + ao);
                ldm_x4(al[mt], sb + 1 * MAT_BYTES + ao);
            }
            #pragma unroll
            for (int p = 0; p < 2; p++) {
                uint32_t bo = bRowOff + (uint32_t)(p * 16) * ROWSTRIDE_B + kByte + bKsel;
                ldm_x4(&bh[p * 4], sb + 2 * MAT_BYTES + bo);
                ldm_x4(&bl[p * 4], sb + 3 * MAT_BYTES + bo);
            }
            #pragma unroll
            for (int mt = 0; mt < 4; mt++)
                #pragma unroll
                for (int nt = 0; nt < 4; nt++)
                    mma16816(acc[mt][nt], ah[mt], bh[nt * 2], bh[nt * 2 + 1]);
            #pragma unroll
            for (int mt = 0; mt < 4; mt++)
                #pragma unroll
                for (int nt = 0; nt < 4; nt++)
                    mma16816(acc[mt][nt], ah[mt], bl[nt * 2], bl[nt * 2 + 1]);
            #pragma unroll
            for (int mt = 0; mt < 4; mt++)
                #pragma unroll
                for (int nt = 0; nt < 4; nt++)
                    mma16816(acc[mt][nt], al[mt], bh[nt * 2], bh[nt * 2 + 1]);
        }
    }
    cp_wait<0>();

    if (mode == 0) {
        const int mrow = mBase + wm * 64 + (lane >> 2);
        const int ncol = nBase + wn * 32 + (lane & 3) * 2;
        #pragma unroll
        for (int mt = 0; mt < 4; mt++)
            #pragma unroll
            for (int nt = 0; nt < 4; nt++) {
                #pragma unroll
                for (int half = 0; half < 2; half++) {
                    float v0 = acc[mt][nt][half * 2 + 0] * scale;
                    float v1 = acc[mt][nt][half * 2 + 1] * scale;
                    __nv_bfloat16 h0 = __float2bfloat16(v0);
                    __nv_bfloat16 h1 = __float2bfloat16(v1);
                    __nv_bfloat16 l0 = __float2bfloat16(v0 - __bfloat162float(h0));
                    __nv_bfloat16 l1 = __float2bfloat16(v1 - __bfloat162float(h1));
                    size_t o = (size_t)(mrow + mt * 16 + half * 8) * EMB + (ncol + nt * 8);
                    *(uint32_t*)(Chi + o) = packbf(h0, h1);
                    *(uint32_t*)(Clo + o) = packbf(l0, l1);
                }
            }
    } else {
        // ---- fused online softmax over this 128x128 logits tile ----
        __syncthreads();   // all warps done with stage smem; reuse it
        float* smax = (float*)smem;              // [128][4]
        float* ss0  = (float*)(smem + 2048);     // [128][4]
        float* ss1  = (float*)(smem + 4096);     // [128][4]

        // vmean values for this thread's 8 columns (cols fixed across mt/half)
        const int colq = (lane & 3) * 2;
        float vmv[8];
        #pragma unroll
        for (int nt = 0; nt < 4; nt++) {
            int c = nBase + wn * 32 + nt * 8 + colq;
            vmv[nt * 2 + 0] = g_vmean[bz * SEQ + c];
            vmv[nt * 2 + 1] = g_vmean[bz * SEQ + c + 1];
        }

        // sweep 1: per-row warp-local max (over this warp's 32 cols)
        #pragma unroll
        for (int mt = 0; mt < 4; mt++) {
            #pragma unroll
            for (int half = 0; half < 2; half++) {
                float mloc = -CUDART_INF_F;
                #pragma unroll
                for (int nt = 0; nt < 4; nt++) {
                    mloc = fmaxf(mloc, fmaxf(acc[mt][nt][half * 2 + 0],
                                             acc[mt][nt][half * 2 + 1]));
                }
                mloc = fmaxf(mloc, __shfl_xor_sync(0xffffffffu, mloc, 1));
                mloc = fmaxf(mloc, __shfl_xor_sync(0xffffffffu, mloc, 2));
                if ((lane & 3) == 0) {
                    int rl = wm * 64 + mt * 16 + half * 8 + (lane >> 2);
                    smax[rl * 4 + wn] = mloc;
                }
            }
        }
        __syncthreads();

        // sweep 2: exp-sums against the tile row max
        #pragma unroll
        for (int mt = 0; mt < 4; mt++) {
            #pragma unroll
            for (int half = 0; half < 2; half++) {
                int rl = wm * 64 + mt * 16 + half * 8 + (lane >> 2);
                float mrow = fmaxf(fmaxf(smax[rl * 4 + 0], smax[rl * 4 + 1]),
                                   fmaxf(smax[rl * 4 + 2], smax[rl * 4 + 3]));
                float t0 = 0.f, t1 = 0.f;
                #pragma unroll
                for (int nt = 0; nt < 4; nt++) {
                    float e0 = __expf(acc[mt][nt][half * 2 + 0] * scale - mrow * scale);
                    float e1 = __expf(acc[mt][nt][half * 2 + 1] * scale - mrow * scale);
                    t0 += e0 + e1;
                    t1 += e0 * vmv[nt * 2 + 0] + e1 * vmv[nt * 2 + 1];
                }
                t0 += __shfl_xor_sync(0xffffffffu, t0, 1);
                t0 += __shfl_xor_sync(0xffffffffu, t0, 2);
                t1 += __shfl_xor_sync(0xffffffffu, t1, 1);
                t1 += __shfl_xor_sync(0xffffffffu, t1, 2);
                if ((lane & 3) == 0) {
                    ss0[rl * 4 + wn] = t0;
                    ss1[rl * 4 + wn] = t1;
                }
            }
        }
        __syncthreads();

        // per-row tile totals + global lock-merge (threads 0..127, one row each)
        if (tid < 128) {
            int rl = tid;
            float m = fmaxf(fmaxf(smax[rl * 4 + 0], smax[rl * 4 + 1]),
                            fmaxf(smax[rl * 4 + 2], smax[rl * 4 + 3])) * scale;
            float t0 = ss0[rl * 4 + 0] + ss0[rl * 4 + 1] + ss0[rl * 4 + 2] + ss0[rl * 4 + 3];
            float t1 = ss1[rl * 4 + 0] + ss1[rl * 4 + 1] + ss1[rl * 4 + 2] + ss1[rl * 4 + 3];
            int gr = bz * SEQ + mBase + rl;

            while (atomicCAS(&g_lock[gr], 0u, 1u) != 0u) { }
            __threadfence();
            float M  = __ldcg(&g_M[gr]);
            float S0 = __ldcg(&g_S0[gr]);
            float S1 = __ldcg(&g_S1[gr]);
            float newM = fmaxf(M, m);
            float eOld = __expf(M - newM);   // 0 when M == -inf
            float eNew = __expf(m - newM);
            __stcg(&g_S0[gr], S0 * eOld + t0 * eNew);
            __stcg(&g_S1[gr], S1 * eOld + t1 * eNew);
            __stcg(&g_M[gr], newM);
            __threadfence();
            atomicExch(&g_lock[gr], 0u);
        }
    }
}

// ---------------------------------------------------------------------------
// Final: out[r] = S1[r] / S0[r]
// ---------------------------------------------------------------------------
__global__ __launch_bounds__(256)
void out_div_kernel(float* __restrict__ out) {
    int i = blockIdx.x * 256 + threadIdx.x;
    out[i] = g_S1[i] / g_S0[i];
}

// ---------------------------------------------------------------------------
extern "C" void kernel_launch(void* const* d_in, const int* in_sizes, int n_in,
                              void* d_out, int out_size) {
    const float* X  = (const float*)d_in[0];
    const float* Wq = (const float*)d_in[1];
    const float* Wk = (const float*)d_in[2];
    const float* Wv = (const float*)d_in[3];
    float* out = (float*)d_out;

    __nv_bfloat16 *Xhi, *Xlo, *Wqh, *Wql, *Wkh, *Wkl, *Mth, *Mtl, *Yh, *Yl;
    cudaGetSymbolAddress((void**)&Xhi, g_Xhi);
    cudaGetSymbolAddress((void**)&Xlo, g_Xlo);
    cudaGetSymbolAddress((void**)&Wqh, g_Wq_hi);
    cudaGetSymbolAddress((void**)&Wql, g_Wq_lo);
    cudaGetSymbolAddress((void**)&Wkh, g_Wk_hi);
    cudaGetSymbolAddress((void**)&Wkl, g_Wk_lo);
    cudaGetSymbolAddress((void**)&Mth, g_Mt_hi);
    cudaGetSymbolAddress((void**)&Mtl, g_Mt_lo);
    cudaGetSymbolAddress((void**)&Yh, g_Yhi);
    cudaGetSymbolAddress((void**)&Yl, g_Ylo);

    cudaFuncSetAttribute(gemm_nt_mma, cudaFuncAttributeMaxDynamicSharedMemorySize, DSMEM_BYTES);

    // 1. prep (split X/Wq/Wk; wvbar; softmax-state init)
    prep1_kernel<<<P_SM_END, 256>>>(X, Wq, Wk, Wv);
    // 2. vmean
    vmean_kernel<<<ROWS / 8, 256>>>(X);

    // 3. Mt = (Wk . Wq^T) / 32  -> split bf16   [1024 x 1024]
    {
        dim3 grid(EMB / CTN, EMB / CTM, 1);
        gemm_nt_mma<<<grid, NTHREADS, DSMEM_BYTES>>>(Wkh, Wkl, Wqh, Wql, 0, 0,
                                                     0, SCALE, Mth, Mtl);
    }

    // 4. Y = X . Mt^T -> split bf16   [16384 x 1024]
    {
        dim3 grid(EMB / CTN, ROWS / CTM, 1);
        gemm_nt_mma<<<grid, NTHREADS, DSMEM_BYTES>>>(Xhi, Xlo, Mth, Mtl, 0, 0,
                                                     0, 1.0f, Yh, Yl);
    }

    // 5. logits = Y . X^T (batched) + FUSED online softmax (no logits write)
    {
        dim3 grid(SEQ / CTN, SEQ / CTM, BATCH);
        gemm_nt_mma<<<grid, NTHREADS, DSMEM_BYTES>>>(Yh, Yl, Xhi, Xlo,
                                                     (size_t)SEQ * EMB, (size_t)SEQ * EMB,
                                                     1, 1.0f, nullptr, nullptr);
    }

    // 6. out = S1 / S0
    out_div_kernel<<<ROWS / 256, 256>>>(out);
}

// round 17
// speedup vs baseline: 1.2276x; 1.2276x over previous
#include <cuda_runtime.h>
#include <cuda_bf16.h>
#include <cstdint>
#include <math_constants.h>

#define BATCH 4
#define SEQ   4096
#define EMB   1024
#define ROWS  (BATCH * SEQ)      // 16384
#define SCALE 0.03125f           // 1/sqrt(1024)
#define NTILE (SEQ / 128)        // 32 logits tiles per row

// GEMM tiling: CTA 128x128, 256 threads (2x4 warps, warp tile 64x32),
// 2-stage cp.async double buffer, 2 CTAs per SM.
#define CTM 128
#define CTN 128
#define KSTAGE 32
#define NSTAGES 2
#define KSTEPS (EMB / KSTAGE)    // 32
#define NTHREADS 256

#define ROWSTRIDE_B 80           // bytes (32 bf16 + pad)
#define MAT_BYTES  (128 * ROWSTRIDE_B)       // 10240
#define STAGE_BYTES (4 * MAT_BYTES)          // 40960
#define DSMEM_BYTES (NSTAGES * STAGE_BYTES)  // 81920 per CTA -> 2 CTAs/SM

// ---------------------------------------------------------------------------
// Scratch (device globals)
// ---------------------------------------------------------------------------
__device__ __nv_bfloat16 g_Xhi[(size_t)ROWS * EMB];
__device__ __nv_bfloat16 g_Xlo[(size_t)ROWS * EMB];
__device__ __nv_bfloat16 g_Wq_hi[EMB * EMB], g_Wq_lo[EMB * EMB];
__device__ __nv_bfloat16 g_Wk_hi[EMB * EMB], g_Wk_lo[EMB * EMB];
__device__ __nv_bfloat16 g_Mt_hi[EMB * EMB], g_Mt_lo[EMB * EMB];   // (Wk Wq^T)/32
__device__ __nv_bfloat16 g_Yhi[(size_t)ROWS * EMB], g_Ylo[(size_t)ROWS * EMB];
__device__ float g_vmean[ROWS];
__device__ float g_wvbar[EMB];
// lock-free split-softmax partials: [row][tile]
__device__ float g_pM[(size_t)ROWS * NTILE];
__device__ float g_pS0[(size_t)ROWS * NTILE];
__device__ float g_pS1[(size_t)ROWS * NTILE];

// ---------------------------------------------------------------------------
// Helpers
// ---------------------------------------------------------------------------
__device__ __forceinline__ uint32_t smem_u32(const void* p) {
    uint32_t a;
    asm("{ .reg .u64 t; cvta.to.shared.u64 t, %1; cvt.u32.u64 %0, t; }" : "=r"(a) : "l"(p));
    return a;
}
__device__ __forceinline__ void cp_async16(uint32_t dst, const void* src) {
    asm volatile("cp.async.cg.shared.global [%0], [%1], 16;" :: "r"(dst), "l"(src) : "memory");
}
__device__ __forceinline__ void cp_commit() {
    asm volatile("cp.async.commit_group;" ::: "memory");
}
template <int NN>
__device__ __forceinline__ void cp_wait() {
    asm volatile("cp.async.wait_group %0;" :: "n"(NN) : "memory");
}
__device__ __forceinline__ void ldm_x4(uint32_t* r, uint32_t addr) {
    asm volatile("ldmatrix.sync.aligned.m8n8.x4.shared.b16 {%0,%1,%2,%3}, [%4];"
                 : "=r"(r[0]), "=r"(r[1]), "=r"(r[2]), "=r"(r[3]) : "r"(addr));
}
__device__ __forceinline__ void mma16816(float* c, const uint32_t* a, uint32_t b0, uint32_t b1) {
    asm volatile("mma.sync.aligned.m16n8k16.row.col.f32.bf16.bf16.f32 "
                 "{%0,%1,%2,%3}, {%4,%5,%6,%7}, {%8,%9}, {%0,%1,%2,%3};"
                 : "+f"(c[0]), "+f"(c[1]), "+f"(c[2]), "+f"(c[3])
                 : "r"(a[0]), "r"(a[1]), "r"(a[2]), "r"(a[3]), "r"(b0), "r"(b1));
}
__device__ __forceinline__ uint32_t packbf(__nv_bfloat16 a, __nv_bfloat16 b) {
    __nv_bfloat162 t = __halves2bfloat162(a, b);
    return *reinterpret_cast<uint32_t*>(&t);
}

// ---------------------------------------------------------------------------
// prep1: range-branched mega-kernel
// ---------------------------------------------------------------------------
#define P_SPLIT_END 16384
#define P_WQ_END    17408
#define P_WK_END    18432
#define P_WV_END    18560

__device__ __forceinline__ void split4(const float4* __restrict__ src,
                                       uint2* __restrict__ hi, uint2* __restrict__ lo, int i) {
    float4 v = src[i];
    __nv_bfloat16 h0 = __float2bfloat16(v.x), h1 = __float2bfloat16(v.y);
    __nv_bfloat16 h2 = __float2bfloat16(v.z), h3 = __float2bfloat16(v.w);
    __nv_bfloat16 l0 = __float2bfloat16(v.x - __bfloat162float(h0));
    __nv_bfloat16 l1 = __float2bfloat16(v.y - __bfloat162float(h1));
    __nv_bfloat16 l2 = __float2bfloat16(v.z - __bfloat162float(h2));
    __nv_bfloat16 l3 = __float2bfloat16(v.w - __bfloat162float(h3));
    hi[i] = make_uint2(packbf(h0, h1), packbf(h2, h3));
    lo[i] = make_uint2(packbf(l0, l1), packbf(l2, l3));
}

__global__ __launch_bounds__(256)
void prep1_kernel(const float* __restrict__ X,
                  const float* __restrict__ Wq,
                  const float* __restrict__ Wk,
                  const float* __restrict__ Wv) {
    const int b = blockIdx.x;
    if (b < P_SPLIT_END) {
        split4((const float4*)X, (uint2*)g_Xhi, (uint2*)g_Xlo, b * 256 + threadIdx.x);
    } else if (b < P_WQ_END) {
        split4((const float4*)Wq, (uint2*)g_Wq_hi, (uint2*)g_Wq_lo,
               (b - P_SPLIT_END) * 256 + threadIdx.x);
    } else if (b < P_WK_END) {
        split4((const float4*)Wk, (uint2*)g_Wk_hi, (uint2*)g_Wk_lo,
               (b - P_WQ_END) * 256 + threadIdx.x);
    } else {
        int row = (b - P_WK_END) * 8 + (threadIdx.x >> 5);
        int lane = threadIdx.x & 31;
        const float* p = Wv + (size_t)row * EMB;
        float s = 0.f;
        #pragma unroll 4
        for (int j = lane; j < EMB; j += 32) s += p[j];
        #pragma unroll
        for (int o = 16; o > 0; o >>= 1) s += __shfl_xor_sync(0xffffffffu, s, o);
        if (lane == 0) g_wvbar[row] = s * (1.0f / (float)EMB);
    }
}

__global__ void vmean_kernel(const float* __restrict__ X) {
    int row = blockIdx.x * (blockDim.x >> 5) + (threadIdx.x >> 5);
    int lane = threadIdx.x & 31;
    if (row >= ROWS) return;
    const float4* p = (const float4*)(X + (size_t)row * EMB);
    const float4* w = (const float4*)g_wvbar;
    float s = 0.f;
    #pragma unroll 8
    for (int j = lane; j < EMB / 4; j += 32) {
        float4 a = p[j], b = w[j];
        s += a.x * b.x + a.y * b.y + a.z * b.z + a.w * b.w;
    }
    #pragma unroll
    for (int o = 16; o > 0; o >>= 1) s += __shfl_xor_sync(0xffffffffu, s, o);
    if (lane == 0) g_vmean[row] = s;
}

// ---------------------------------------------------------------------------
// bf16x2-split NT GEMM: 256 threads, 2x4 warps, warp tile 64x32,
// 2-stage double buffer, 2 CTAs/SM.
// mode 0: write C as split bf16 (scaled)
// mode 1: fused softmax partials — per-row (m, s0, s1) of this tile written
//         LOCK-FREE to g_pM/g_pS0/g_pS1 at [row*NTILE + blockIdx.x].
// ---------------------------------------------------------------------------
__global__ __launch_bounds__(NTHREADS, 2)
void gemm_nt_mma(const __nv_bfloat16* __restrict__ Ahi, const __nv_bfloat16* __restrict__ Alo,
                 const __nv_bfloat16* __restrict__ Bhi, const __nv_bfloat16* __restrict__ Blo,
                 size_t aBatch, size_t bBatch, int mode, float scale,
                 __nv_bfloat16* __restrict__ Chi, __nv_bfloat16* __restrict__ Clo) {
    extern __shared__ char smem[];
    const uint32_t sbase = smem_u32(smem);
    const int tid = threadIdx.x;
    const int lane = tid & 31;
    const int wid = tid >> 5;
    const int wm = wid >> 2;          // 0..1  -> 64 rows each
    const int wn = wid & 3;           // 0..3  -> 32 cols each
    const int bz = blockIdx.z;
    const int mBase = blockIdx.y * CTM;
    const int nBase = blockIdx.x * CTN;

    const __nv_bfloat16* gsrc[4];
    gsrc[0] = Ahi + (size_t)bz * aBatch + (size_t)mBase * EMB;
    gsrc[1] = Alo + (size_t)bz * aBatch + (size_t)mBase * EMB;
    gsrc[2] = Bhi + (size_t)bz * bBatch + (size_t)nBase * EMB;
    gsrc[3] = Blo + (size_t)bz * bBatch + (size_t)nBase * EMB;

    const int r0 = tid >> 2, s0i = tid & 3;
    const int r1 = 64 + (tid >> 2);

    const uint32_t aRowOff = (uint32_t)(wm * 64 + (lane & 15)) * ROWSTRIDE_B;
    const uint32_t aKsel = ((lane >> 4) & 1) * 16;
    const uint32_t bRowOff = (uint32_t)(wn * 32 + ((lane >> 4) & 1) * 8 + (lane & 7)) * ROWSTRIDE_B;
    const uint32_t bKsel = ((lane >> 3) & 1) * 16;

    float acc[4][4][4];
    #pragma unroll
    for (int i = 0; i < 4; i++)
        #pragma unroll
        for (int j = 0; j < 4; j++)
            #pragma unroll
            for (int q = 0; q < 4; q++) acc[i][j][q] = 0.f;

    auto load_stage = [&](int k0, int buf) {
        uint32_t sb = sbase + buf * STAGE_BYTES;
        #pragma unroll
        for (int m = 0; m < 4; m++) {
            const __nv_bfloat16* g = gsrc[m] + k0 * KSTAGE;
            cp_async16(sb + m * MAT_BYTES + r0 * ROWSTRIDE_B + s0i * 16,
                       g + (size_t)r0 * EMB + s0i * 8);
            cp_async16(sb + m * MAT_BYTES + r1 * ROWSTRIDE_B + s0i * 16,
                       g + (size_t)r1 * EMB + s0i * 8);
        }
    };

    load_stage(0, 0);
    cp_commit();

    for (int k0 = 0; k0 < KSTEPS; k0++) {
        cp_wait<0>();
        __syncthreads();
        if (k0 + 1 < KSTEPS)
            load_stage(k0 + 1, (k0 + 1) & 1);
        cp_commit();

        const uint32_t sb = sbase + (k0 & 1) * STAGE_BYTES;
        #pragma unroll
        for (int kk = 0; kk < 2; kk++) {
            const uint32_t kByte = kk * 32;
            uint32_t ah[4][4], al[4][4], bh[8], bl[8];
            #pragma unroll
            for (int mt = 0; mt < 4; mt++) {
                uint32_t ao = aRowOff + (uint32_t)(mt * 16) * ROWSTRIDE_B + kByte + aKsel;
                ldm_x4(ah[mt], sb + 0 * MAT_BYTES + ao);
                ldm_x4(al[mt], sb + 1 * MAT_BYTES + ao);
            }
            #pragma unroll
            for (int p = 0; p < 2; p++) {
                uint32_t bo = bRowOff + (uint32_t)(p * 16) * ROWSTRIDE_B + kByte + bKsel;
                ldm_x4(&bh[p * 4], sb + 2 * MAT_BYTES + bo);
                ldm_x4(&bl[p * 4], sb + 3 * MAT_BYTES + bo);
            }
            #pragma unroll
            for (int mt = 0; mt < 4; mt++)
                #pragma unroll
                for (int nt = 0; nt < 4; nt++)
                    mma16816(acc[mt][nt], ah[mt], bh[nt * 2], bh[nt * 2 + 1]);
            #pragma unroll
            for (int mt = 0; mt < 4; mt++)
                #pragma unroll
                for (int nt = 0; nt < 4; nt++)
                    mma16816(acc[mt][nt], ah[mt], bl[nt * 2], bl[nt * 2 + 1]);
            #pragma unroll
            for (int mt = 0; mt < 4; mt++)
                #pragma unroll
                for (int nt = 0; nt < 4; nt++)
                    mma16816(acc[mt][nt], al[mt], bh[nt * 2], bh[nt * 2 + 1]);
        }
    }
    cp_wait<0>();

    if (mode == 0) {
        const int mrow = mBase + wm * 64 + (lane >> 2);
        const int ncol = nBase + wn * 32 + (lane & 3) * 2;
        #pragma unroll
        for (int mt = 0; mt < 4; mt++)
            #pragma unroll
            for (int nt = 0; nt < 4; nt++) {
                #pragma unroll
                for (int half = 0; half < 2; half++) {
                    float v0 = acc[mt][nt][half * 2 + 0] * scale;
                    float v1 = acc[mt][nt][half * 2 + 1] * scale;
                    __nv_bfloat16 h0 = __float2bfloat16(v0);
                    __nv_bfloat16 h1 = __float2bfloat16(v1);
                    __nv_bfloat16 l0 = __float2bfloat16(v0 - __bfloat162float(h0));
                    __nv_bfloat16 l1 = __float2bfloat16(v1 - __bfloat162float(h1));
                    size_t o = (size_t)(mrow + mt * 16 + half * 8) * EMB + (ncol + nt * 8);
                    *(uint32_t*)(Chi + o) = packbf(h0, h1);
                    *(uint32_t*)(Clo + o) = packbf(l0, l1);
                }
            }
    } else {
        // ---- per-tile softmax partials (lock-free) ----
        __syncthreads();   // stage smem no longer needed; reuse it
        float* smax = (float*)smem;              // [128][4]
        float* ss0  = (float*)(smem + 2048);     // [128][4]
        float* ss1  = (float*)(smem + 4096);     // [128][4]

        const int colq = (lane & 3) * 2;
        float vmv[8];
        #pragma unroll
        for (int nt = 0; nt < 4; nt++) {
            int c = nBase + wn * 32 + nt * 8 + colq;
            vmv[nt * 2 + 0] = g_vmean[bz * SEQ + c];
            vmv[nt * 2 + 1] = g_vmean[bz * SEQ + c + 1];
        }

        // sweep 1: warp-local row max
        #pragma unroll
        for (int mt = 0; mt < 4; mt++) {
            #pragma unroll
            for (int half = 0; half < 2; half++) {
                float mloc = -CUDART_INF_F;
                #pragma unroll
                for (int nt = 0; nt < 4; nt++) {
                    mloc = fmaxf(mloc, fmaxf(acc[mt][nt][half * 2 + 0],
                                             acc[mt][nt][half * 2 + 1]));
                }
                mloc = fmaxf(mloc, __shfl_xor_sync(0xffffffffu, mloc, 1));
                mloc = fmaxf(mloc, __shfl_xor_sync(0xffffffffu, mloc, 2));
                if ((lane & 3) == 0) {
                    int rl = wm * 64 + mt * 16 + half * 8 + (lane >> 2);
                    smax[rl * 4 + wn] = mloc;
                }
            }
        }
        __syncthreads();

        // sweep 2: exp-sums vs tile row max
        #pragma unroll
        for (int mt = 0; mt < 4; mt++) {
            #pragma unroll
            for (int half = 0; half < 2; half++) {
                int rl = wm * 64 + mt * 16 + half * 8 + (lane >> 2);
                float mrow = fmaxf(fmaxf(smax[rl * 4 + 0], smax[rl * 4 + 1]),
                                   fmaxf(smax[rl * 4 + 2], smax[rl * 4 + 3]));
                float t0 = 0.f, t1 = 0.f;
                #pragma unroll
                for (int nt = 0; nt < 4; nt++) {
                    float e0 = __expf(acc[mt][nt][half * 2 + 0] * scale - mrow * scale);
                    float e1 = __expf(acc[mt][nt][half * 2 + 1] * scale - mrow * scale);
                    t0 += e0 + e1;
                    t1 += e0 * vmv[nt * 2 + 0] + e1 * vmv[nt * 2 + 1];
                }
                t0 += __shfl_xor_sync(0xffffffffu, t0, 1);
                t0 += __shfl_xor_sync(0xffffffffu, t0, 2);
                t1 += __shfl_xor_sync(0xffffffffu, t1, 1);
                t1 += __shfl_xor_sync(0xffffffffu, t1, 2);
                if ((lane & 3) == 0) {
                    ss0[rl * 4 + wn] = t0;
                    ss1[rl * 4 + wn] = t1;
                }
            }
        }
        __syncthreads();

        // per-row tile totals -> disjoint global slots (no locks)
        if (tid < 128) {
            int rl = tid;
            float m = fmaxf(fmaxf(smax[rl * 4 + 0], smax[rl * 4 + 1]),
                            fmaxf(smax[rl * 4 + 2], smax[rl * 4 + 3])) * scale;
            float t0 = ss0[rl * 4 + 0] + ss0[rl * 4 + 1] + ss0[rl * 4 + 2] + ss0[rl * 4 + 3];
            float t1 = ss1[rl * 4 + 0] + ss1[rl * 4 + 1] + ss1[rl * 4 + 2] + ss1[rl * 4 + 3];
            size_t slot = (size_t)(bz * SEQ + mBase + rl) * NTILE + blockIdx.x;
            g_pM[slot]  = m;
            g_pS0[slot] = t0;
            g_pS1[slot] = t1;
        }
    }
}

// ---------------------------------------------------------------------------
// Merge partials: one warp per row (lane = tile), out[r] = S1/S0
// ---------------------------------------------------------------------------
__global__ __launch_bounds__(256)
void merge_kernel(float* __restrict__ out) {
    int row = blockIdx.x * 8 + (threadIdx.x >> 5);
    int lane = threadIdx.x & 31;
    size_t slot = (size_t)row * NTILE + lane;
    float m = g_pM[slot];
    float s0 = g_pS0[slot];
    float s1 = g_pS1[slot];
    float M = m;
    #pragma unroll
    for (int o = 16; o > 0; o >>= 1) M = fmaxf(M, __shfl_xor_sync(0xffffffffu, M, o));
    float e = __expf(m - M);
    s0 *= e;
    s1 *= e;
    #pragma unroll
    for (int o = 16; o > 0; o >>= 1) {
        s0 += __shfl_xor_sync(0xffffffffu, s0, o);
        s1 += __shfl_xor_sync(0xffffffffu, s1, o);
    }
    if (lane == 0) out[row] = s1 / s0;
}

// ---------------------------------------------------------------------------
extern "C" void kernel_launch(void* const* d_in, const int* in_sizes, int n_in,
                              void* d_out, int out_size) {
    const float* X  = (const float*)d_in[0];
    const float* Wq = (const float*)d_in[1];
    const float* Wk = (const float*)d_in[2];
    const float* Wv = (const float*)d_in[3];
    float* out = (float*)d_out;

    __nv_bfloat16 *Xhi, *Xlo, *Wqh, *Wql, *Wkh, *Wkl, *Mth, *Mtl, *Yh, *Yl;
    cudaGetSymbolAddress((void**)&Xhi, g_Xhi);
    cudaGetSymbolAddress((void**)&Xlo, g_Xlo);
    cudaGetSymbolAddress((void**)&Wqh, g_Wq_hi);
    cudaGetSymbolAddress((void**)&Wql, g_Wq_lo);
    cudaGetSymbolAddress((void**)&Wkh, g_Wk_hi);
    cudaGetSymbolAddress((void**)&Wkl, g_Wk_lo);
    cudaGetSymbolAddress((void**)&Mth, g_Mt_hi);
    cudaGetSymbolAddress((void**)&Mtl, g_Mt_lo);
    cudaGetSymbolAddress((void**)&Yh, g_Yhi);
    cudaGetSymbolAddress((void**)&Yl, g_Ylo);

    cudaFuncSetAttribute(gemm_nt_mma, cudaFuncAttributeMaxDynamicSharedMemorySize, DSMEM_BYTES);

    // 1. prep (split X/Wq/Wk; wvbar)
    prep1_kernel<<<P_WV_END, 256>>>(X, Wq, Wk, Wv);
    // 2. vmean
    vmean_kernel<<<ROWS / 8, 256>>>(X);

    // 3. Mt = (Wk . Wq^T) / 32  -> split bf16   [1024 x 1024]
    {
        dim3 grid(EMB / CTN, EMB / CTM, 1);
        gemm_nt_mma<<<grid, NTHREADS, DSMEM_BYTES>>>(Wkh, Wkl, Wqh, Wql, 0, 0,
                                                     0, SCALE, Mth, Mtl);
    }

    // 4. Y = X . Mt^T -> split bf16   [16384 x 1024]
    {
        dim3 grid(EMB / CTN, ROWS / CTM, 1);
        gemm_nt_mma<<<grid, NTHREADS, DSMEM_BYTES>>>(Xhi, Xlo, Mth, Mtl, 0, 0,
                                                     0, 1.0f, Yh, Yl);
    }

    // 5. logits = Y . X^T (batched) + fused softmax partials (lock-free)
    {
        dim3 grid(SEQ / CTN, SEQ / CTM, BATCH);
        gemm_nt_mma<<<grid, NTHREADS, DSMEM_BYTES>>>(Yh, Yl, Xhi, Xlo,
                                                     (size_t)SEQ * EMB, (size_t)SEQ * EMB,
                                                     1, 1.0f, nullptr, nullptr);
    }

    // 6. merge partials -> out
    merge_kernel<<<ROWS / 8, 256>>>(out);
}